// round 1
// baseline (speedup 1.0000x reference)
#include <cuda_runtime.h>
#include <math.h>

#define B_    2
#define S_    2048
#define D_    2048
#define H_    16
#define KVH_  8
#define HD_   128
#define KVR_  512
#define NROWS 4096          // B_*S_

// ---------------- scratch (device globals: no allocs allowed) ----------------
__device__ float g_Q[NROWS * 4096];      // (b,s,h,256) nope|rope(pe)
__device__ float g_KV[NROWS * 640];      // x @ wkv_a
__device__ float g_KVC[NROWS * 512];     // layernormed latent
__device__ float g_KPE[NROWS * 128];     // roped k_pe
__device__ float g_KVB[NROWS * 2048];    // (b,s,kvh,256) k_nope|v
__device__ float g_ATTN[NROWS * 2048];   // attention output (b,s,h,128)
__device__ float g_COS[S_ * 64];
__device__ float g_SIN[S_ * 64];

// ---------------- rope cos/sin table ----------------
__global__ void rope_table_kernel(const int* __restrict__ pos,
                                  float* __restrict__ cosT, float* __restrict__ sinT)
{
    int s = blockIdx.x, i = threadIdx.x;          // 2048 blocks x 64 threads
    double e = (double)i / 64.0;                   // (2i)/HD, exact
    float t = (float)pow(10000.0, e);              // correctly-rounded f32 pow
    float freq = (1.0f / t) * 40.0f;               // match ref op order
    float ang = (float)pos[s] * freq;              // fp32 rounding like ref
    cosT[s * 64 + i] = (float)cos((double)ang);
    sinT[s * 64 + i] = (float)sin((double)ang);
}

// ---------------- layernorm + rope (k_pe and q_pe in-place) ----------------
__global__ __launch_bounds__(256) void ln_rope_kernel(
    const float* __restrict__ KV, const float* __restrict__ lnscale,
    float* __restrict__ Q, float* __restrict__ KVC, float* __restrict__ KPE,
    const float* __restrict__ cosT, const float* __restrict__ sinT)
{
    const int row = blockIdx.x;
    const int tid = threadIdx.x;
    const int s = row & (S_ - 1);
    const float* kvr = KV + (size_t)row * 640;

    float v0 = kvr[tid], v1 = kvr[tid + 256];
    float sum = v0 + v1, sq = v0 * v0 + v1 * v1;
#pragma unroll
    for (int o = 16; o > 0; o >>= 1) {
        sum += __shfl_xor_sync(0xffffffffu, sum, o);
        sq  += __shfl_xor_sync(0xffffffffu, sq, o);
    }
    __shared__ float red[16];
    if ((tid & 31) == 0) { red[tid >> 5] = sum; red[(tid >> 5) + 8] = sq; }
    __syncthreads();
    float tot = 0.f, tot2 = 0.f;
#pragma unroll
    for (int i = 0; i < 8; i++) { tot += red[i]; tot2 += red[i + 8]; }
    float mean = tot * (1.f / 512.f);
    float var  = tot2 * (1.f / 512.f) - mean * mean;
    float inv  = rsqrtf(var + 1e-5f);
    KVC[(size_t)row * 512 + tid]       = (v0 - mean) * inv * lnscale[tid];
    KVC[(size_t)row * 512 + tid + 256] = (v1 - mean) * inv * lnscale[tid + 256];

    if (tid < 64) {
        float c = cosT[s * 64 + tid], sn = sinT[s * 64 + tid];
        float xr = kvr[512 + 2 * tid], xi = kvr[512 + 2 * tid + 1];
        KPE[(size_t)row * 128 + 2 * tid]     = xr * c - xi * sn;
        KPE[(size_t)row * 128 + 2 * tid + 1] = xr * sn + xi * c;
    }
#pragma unroll
    for (int t = tid; t < 1024; t += 256) {          // 16 heads * 64 pairs
        int hh = t >> 6, i = t & 63;
        float c = cosT[s * 64 + i], sn = sinT[s * 64 + i];
        float* qp = Q + (size_t)row * 4096 + hh * 256 + 128 + 2 * i;
        float xr = qp[0], xi = qp[1];
        qp[0] = xr * c - xi * sn;
        qp[1] = xr * sn + xi * c;
    }
}

// ---------------- fp32 SIMT GEMM: C[M,N] = A[M,K] @ B[K,N] ----------------
// BM=BN=128, BK=16, 256 threads, 8x8 per thread (rows ty*8+i, cols tx+16j).
__global__ __launch_bounds__(256) void sgemm128(
    const float* __restrict__ A, const float* __restrict__ B,
    float* __restrict__ C, int M, int N, int K)
{
    __shared__ float As[16 * 132];   // transposed, padded
    __shared__ float Bs[16 * 128];
    const int tid = threadIdx.x;
    const int tx = tid & 15, ty = tid >> 4;
    const int bm = blockIdx.y << 7, bn = blockIdx.x << 7;
    const float* Ab = A + (size_t)bm * K;
    const float* Bb = B + bn;
    float acc[8][8] = {};

    for (int k0 = 0; k0 < K; k0 += 16) {
#pragma unroll
        for (int l = 0; l < 2; l++) {
            int f = tid + (l << 8);
            int ar = f >> 2, ac = (f & 3) << 2;
            float4 av = *(const float4*)(Ab + (size_t)ar * K + k0 + ac);
            As[(ac + 0) * 132 + ar] = av.x;
            As[(ac + 1) * 132 + ar] = av.y;
            As[(ac + 2) * 132 + ar] = av.z;
            As[(ac + 3) * 132 + ar] = av.w;
            int br = f >> 5, bc = (f & 31) << 2;
            *(float4*)(Bs + br * 128 + bc) =
                *(const float4*)(Bb + (size_t)(k0 + br) * N + bc);
        }
        __syncthreads();
#pragma unroll
        for (int k = 0; k < 16; k++) {
            float a[8], b[8];
            *(float4*)(a)     = *(const float4*)(As + k * 132 + ty * 8);
            *(float4*)(a + 4) = *(const float4*)(As + k * 132 + ty * 8 + 4);
#pragma unroll
            for (int j = 0; j < 8; j++) b[j] = Bs[k * 128 + tx + (j << 4)];
#pragma unroll
            for (int i = 0; i < 8; i++)
#pragma unroll
                for (int j = 0; j < 8; j++)
                    acc[i][j] = fmaf(a[i], b[j], acc[i][j]);
        }
        __syncthreads();
    }
#pragma unroll
    for (int i = 0; i < 8; i++) {
        float* Cr = C + (size_t)(bm + ty * 8 + i) * N + bn;
#pragma unroll
        for (int j = 0; j < 8; j++) Cr[tx + (j << 4)] = acc[i][j];
    }
}

// ---------------- flash attention (causal, online softmax) ----------------
// Block: 64 q-rows x one (b,h). Tiles of 64 k-rows. 256 thr = (ty 0..15) x (tx 0..15).
// Scores: thread tile rows ty*4+i, cols tx+16j. O cols tx+16j (j<8).
#define QKS 68     // padded inner dim of transposed Q/K smem
#define FLASH_SMEM ((2 * 256 * QKS + 64 * 128 + 64 * 68) * 4)

__global__ __launch_bounds__(256) void flash_kernel(
    const float* __restrict__ Q, const float* __restrict__ KVB,
    const float* __restrict__ KPE, float* __restrict__ ATTN)
{
    extern __shared__ float smf[];
    float* Qs = smf;                  // [256][QKS]  (d-major, transposed)
    float* Ks = Qs + 256 * QKS;       // [256][QKS]
    float* Vs = Ks + 256 * QKS;       // [64][128]   (row-major)
    float* Ps = Vs + 64 * 128;        // [64][68]

    const int tid = threadIdx.x;
    const int tx = tid & 15, ty = tid >> 4;
    const int qi = blockIdx.x, h = blockIdx.y, b = blockIdx.z;
    const int kvh = h >> 1;
    const int qb = b * S_ + qi * 64;

    // load Q tile (transposed into smem; conflict-free stores: r varies per lane)
#pragma unroll
    for (int l = 0; l < 16; l++) {
        int f = tid + (l << 8);
        int r = f & 63, c = f >> 6;
        float4 v = *(const float4*)(Q + (size_t)(qb + r) * 4096 + h * 256 + c * 4);
        Qs[(c * 4 + 0) * QKS + r] = v.x;
        Qs[(c * 4 + 1) * QKS + r] = v.y;
        Qs[(c * 4 + 2) * QKS + r] = v.z;
        Qs[(c * 4 + 3) * QKS + r] = v.w;
    }

    float m[4], lsum[4], o[4][8];
#pragma unroll
    for (int i = 0; i < 4; i++) {
        m[i] = -INFINITY; lsum[i] = 0.f;
#pragma unroll
        for (int j = 0; j < 8; j++) o[i][j] = 0.f;
    }
    const float scale = 0.08838834764831845f;   // 128^-0.5

    for (int kt = 0; kt <= qi; kt++) {
        const int kb = b * S_ + kt * 64;
        __syncthreads();   // prior PV done with Ks/Vs/Ps
        // load K tile: [k_nope (KVB) | k_pe (KPE)] transposed
#pragma unroll
        for (int l = 0; l < 16; l++) {
            int f = tid + (l << 8);
            int r = f & 63, c = f >> 6;
            float4 v;
            if (c < 32)
                v = *(const float4*)(KVB + (size_t)(kb + r) * 2048 + kvh * 256 + c * 4);
            else
                v = *(const float4*)(KPE + (size_t)(kb + r) * 128 + (c - 32) * 4);
            Ks[(c * 4 + 0) * QKS + r] = v.x;
            Ks[(c * 4 + 1) * QKS + r] = v.y;
            Ks[(c * 4 + 2) * QKS + r] = v.z;
            Ks[(c * 4 + 3) * QKS + r] = v.w;
        }
        // load V tile
#pragma unroll
        for (int l = 0; l < 8; l++) {
            int f = tid + (l << 8);
            int r = f >> 5, c = (f & 31) << 2;
            *(float4*)(Vs + r * 128 + c) =
                *(const float4*)(KVB + (size_t)(kb + r) * 2048 + kvh * 256 + 128 + c);
        }
        __syncthreads();

        // scores: s[i][j] = q(r=ty*4+i) . k(c=tx+16j) over 256 dims
        float s[4][4] = {};
#pragma unroll 8
        for (int d = 0; d < 256; d++) {
            float4 q4 = *(const float4*)(Qs + d * QKS + ty * 4);  // broadcast, no conflict
            float kvv[4];
#pragma unroll
            for (int j = 0; j < 4; j++) kvv[j] = Ks[d * QKS + tx + (j << 4)];
            s[0][0] = fmaf(q4.x, kvv[0], s[0][0]); s[0][1] = fmaf(q4.x, kvv[1], s[0][1]);
            s[0][2] = fmaf(q4.x, kvv[2], s[0][2]); s[0][3] = fmaf(q4.x, kvv[3], s[0][3]);
            s[1][0] = fmaf(q4.y, kvv[0], s[1][0]); s[1][1] = fmaf(q4.y, kvv[1], s[1][1]);
            s[1][2] = fmaf(q4.y, kvv[2], s[1][2]); s[1][3] = fmaf(q4.y, kvv[3], s[1][3]);
            s[2][0] = fmaf(q4.z, kvv[0], s[2][0]); s[2][1] = fmaf(q4.z, kvv[1], s[2][1]);
            s[2][2] = fmaf(q4.z, kvv[2], s[2][2]); s[2][3] = fmaf(q4.z, kvv[3], s[2][3]);
            s[3][0] = fmaf(q4.w, kvv[0], s[3][0]); s[3][1] = fmaf(q4.w, kvv[1], s[3][1]);
            s[3][2] = fmaf(q4.w, kvv[2], s[3][2]); s[3][3] = fmaf(q4.w, kvv[3], s[3][3]);
        }

        const bool diag = (kt == qi);
#pragma unroll
        for (int i = 0; i < 4; i++) {
            float mt;
#pragma unroll
            for (int j = 0; j < 4; j++) {
                s[i][j] *= scale;
                if (diag && (tx + (j << 4)) > (ty * 4 + i)) s[i][j] = -1e9f;
            }
            mt = fmaxf(fmaxf(s[i][0], s[i][1]), fmaxf(s[i][2], s[i][3]));
#pragma unroll
            for (int ofs = 8; ofs > 0; ofs >>= 1)
                mt = fmaxf(mt, __shfl_xor_sync(0xffffffffu, mt, ofs));
            float mnew = fmaxf(m[i], mt);
            float alpha = __expf(m[i] - mnew);
            float rs = 0.f;
#pragma unroll
            for (int j = 0; j < 4; j++) {
                float p = __expf(s[i][j] - mnew);
                rs += p;
                Ps[(ty * 4 + i) * 68 + tx + (j << 4)] = p;
            }
#pragma unroll
            for (int ofs = 8; ofs > 0; ofs >>= 1)
                rs += __shfl_xor_sync(0xffffffffu, rs, ofs);
            lsum[i] = lsum[i] * alpha + rs;
            m[i] = mnew;
#pragma unroll
            for (int j = 0; j < 8; j++) o[i][j] *= alpha;
        }
        __syncthreads();   // Ps visible

        // O += P @ V
#pragma unroll 4
        for (int k = 0; k < 64; k++) {
            float pv[4];
#pragma unroll
            for (int i = 0; i < 4; i++) pv[i] = Ps[(ty * 4 + i) * 68 + k];
#pragma unroll
            for (int j = 0; j < 8; j++) {
                float vv = Vs[k * 128 + tx + (j << 4)];
#pragma unroll
                for (int i = 0; i < 4; i++) o[i][j] = fmaf(pv[i], vv, o[i][j]);
            }
        }
    }

#pragma unroll
    for (int i = 0; i < 4; i++) {
        float inv = 1.f / lsum[i];
        float* dst = ATTN + (size_t)(qb + ty * 4 + i) * 2048 + h * 128;
#pragma unroll
        for (int j = 0; j < 8; j++) dst[tx + (j << 4)] = o[i][j] * inv;
    }
}

// ---------------- launcher ----------------
extern "C" void kernel_launch(void* const* d_in, const int* in_sizes, int n_in,
                              void* d_out, int out_size)
{
    const float* x        = (const float*)d_in[0];
    const float* wq       = (const float*)d_in[1];
    const float* wkv_a    = (const float*)d_in[2];
    const float* kv_scale = (const float*)d_in[3];
    const float* wkv_b    = (const float*)d_in[4];
    const float* wo       = (const float*)d_in[5];
    // d_in[6] attention_mask: pure causal, applied analytically
    const int* pos        = (const int*)d_in[7];
    float* out            = (float*)d_out;

    float *Q, *KV, *KVC, *KPE, *KVB, *ATTN, *cosT, *sinT;
    cudaGetSymbolAddress((void**)&Q,    g_Q);
    cudaGetSymbolAddress((void**)&KV,   g_KV);
    cudaGetSymbolAddress((void**)&KVC,  g_KVC);
    cudaGetSymbolAddress((void**)&KPE,  g_KPE);
    cudaGetSymbolAddress((void**)&KVB,  g_KVB);
    cudaGetSymbolAddress((void**)&ATTN, g_ATTN);
    cudaGetSymbolAddress((void**)&cosT, g_COS);
    cudaGetSymbolAddress((void**)&sinT, g_SIN);

    cudaFuncSetAttribute(flash_kernel,
                         cudaFuncAttributeMaxDynamicSharedMemorySize, FLASH_SMEM);

    dim3 blk(256);
    sgemm128<<<dim3(32, 32), blk>>>(x, wq, Q, 4096, 4096, 2048);      // q proj
    sgemm128<<<dim3(5, 32),  blk>>>(x, wkv_a, KV, 4096, 640, 2048);   // kv_a proj
    rope_table_kernel<<<S_, 64>>>(pos, cosT, sinT);
    ln_rope_kernel<<<NROWS, blk>>>(KV, kv_scale, Q, KVC, KPE, cosT, sinT);
    sgemm128<<<dim3(16, 32), blk>>>(KVC, wkv_b, KVB, 4096, 2048, 512); // kv_b proj
    flash_kernel<<<dim3(32, H_, B_), blk, FLASH_SMEM>>>(Q, KVB, KPE, ATTN);
    sgemm128<<<dim3(16, 32), blk>>>(ATTN, wo, out, 4096, 2048, 2048);  // out proj
}

// round 3
// speedup vs baseline: 1.4285x; 1.4285x over previous
#include <cuda_runtime.h>
#include <cuda_bf16.h>
#include <cstdint>
#include <math.h>

#define B_    2
#define S_    2048
#define H_    16
#define NROWS 4096          // B_*S_

// ---------------- scratch (device globals: no allocs allowed) ----------------
__device__ float g_Q[NROWS * 4096];                  // (b,s,h,256) nope|rope(pe)  fp32
__device__ float g_KV[NROWS * 768];                  // x @ wkv_a (padded 640->768)
__device__ float g_KPE[NROWS * 128];                 // roped k_pe
__device__ float g_KVB[NROWS * 2048];                // (b,s,kvh,256) k_nope|v fp32
__device__ float g_COS[S_ * 64];
__device__ float g_SIN[S_ * 64];
// bf16 split-cat buffers: A side = [hi, lo, hi], B side (transposed weights) = [hi, hi, lo]
__device__ __nv_bfloat16 g_Xc[NROWS * 6144];         // x cat           [4096, 3*2048]
__device__ __nv_bfloat16 g_KVCc[NROWS * 1536];       // kv_c cat        [4096, 3*512]
__device__ __nv_bfloat16 g_ATTNc[NROWS * 6144];      // attn cat        [4096, 3*2048]
__device__ __nv_bfloat16 g_WqT[4096 * 6144];         // wq^T cat        [4096, 3*2048]
__device__ __nv_bfloat16 g_WkvaT[768 * 6144];        // wkv_a^T cat     [768(pad), 3*2048]
__device__ __nv_bfloat16 g_WkvbT[2048 * 1536];       // wkv_b^T cat     [2048, 3*512]
__device__ __nv_bfloat16 g_WoT[2048 * 6144];         // wo^T cat        [2048, 3*2048]

// ================= helpers =================
__device__ __forceinline__ uint32_t smem_u32(const void* p) {
    uint32_t a;
    asm("{ .reg .u64 t; cvta.to.shared.u64 t, %1; cvt.u32.u64 %0, t; }" : "=r"(a) : "l"(p));
    return a;
}
__device__ __forceinline__ void cp_async16(uint32_t saddr, const void* gaddr) {
    asm volatile("cp.async.cg.shared.global [%0], [%1], 16;" :: "r"(saddr), "l"(gaddr));
}
__device__ __forceinline__ void cp_commit() { asm volatile("cp.async.commit_group;"); }
__device__ __forceinline__ void ldmatrix_x4(uint32_t& r0, uint32_t& r1, uint32_t& r2,
                                            uint32_t& r3, uint32_t addr) {
    asm volatile("ldmatrix.sync.aligned.m8n8.x4.shared.b16 {%0,%1,%2,%3}, [%4];"
                 : "=r"(r0), "=r"(r1), "=r"(r2), "=r"(r3) : "r"(addr));
}
__device__ __forceinline__ void mma16816(float* c, const uint32_t* a, const uint32_t* b) {
    asm volatile(
        "mma.sync.aligned.m16n8k16.row.col.f32.bf16.bf16.f32 "
        "{%0,%1,%2,%3}, {%4,%5,%6,%7}, {%8,%9}, {%0,%1,%2,%3};"
        : "+f"(c[0]), "+f"(c[1]), "+f"(c[2]), "+f"(c[3])
        : "r"(a[0]), "r"(a[1]), "r"(a[2]), "r"(a[3]), "r"(b[0]), "r"(b[1]));
}
__device__ __forceinline__ void split_bf16(float x, __nv_bfloat16& h, __nv_bfloat16& l) {
    h = __float2bfloat16(x);
    l = __float2bfloat16(x - __bfloat162float(h));
}

// ================= HMMA split-bf16 GEMM =================
// C[M,N] (fp32, row stride N) = Acat[M,K3] @ Bcat[N,K3]^T.
// CTA tile 128x128, BK=32, 8 warps (2 M x 4 N), warp tile 64x32 via m16n8k16.
#define APAD 40   // smem row length in bf16 (32 data + 8 pad) -> conflict-free ldmatrix

__global__ __launch_bounds__(256) void mma_gemm(
    const __nv_bfloat16* __restrict__ A, const __nv_bfloat16* __restrict__ Bt,
    float* __restrict__ C, int N, int K3)
{
    __shared__ __nv_bfloat16 As[2][128 * APAD];
    __shared__ __nv_bfloat16 Bs[2][128 * APAD];

    const int tid = threadIdx.x, wid = tid >> 5, lane = tid & 31;
    const int bm = blockIdx.y << 7, bn = blockIdx.x << 7;
    const int wm = (wid & 1) << 6;          // 0 / 64
    const int wn = (wid >> 1) << 5;         // 0 / 32 / 64 / 96
    const __nv_bfloat16* Ab = A + (size_t)bm * K3;
    const __nv_bfloat16* Bb = Bt + (size_t)bn * K3;
    const uint32_t sA = smem_u32(As), sB = smem_u32(Bs);
    const int nk = K3 >> 5;

    float acc[4][4][4];
#pragma unroll
    for (int i = 0; i < 4; i++)
#pragma unroll
        for (int j = 0; j < 4; j++)
#pragma unroll
            for (int k = 0; k < 4; k++) acc[i][j][k] = 0.f;

    // per-thread load coords: 512 chunks of 16B per tile, 2 per thread
    const int r0 = tid >> 2, c0 = (tid & 3) << 3;            // chunk 0: row, col(bf16)
    const int r1 = (tid + 256) >> 2;                         // chunk 1 (same c0 pattern)

#define LOAD_STAGE(kt, s) do {                                                        \
    size_t kb = (size_t)(kt) << 5;                                                    \
    cp_async16(sA + (s) * 128 * APAD * 2 + (r0 * APAD + c0) * 2,                      \
               Ab + (size_t)r0 * K3 + kb + c0);                                       \
    cp_async16(sA + (s) * 128 * APAD * 2 + (r1 * APAD + c0) * 2,                      \
               Ab + (size_t)r1 * K3 + kb + c0);                                       \
    cp_async16(sB + (s) * 128 * APAD * 2 + (r0 * APAD + c0) * 2,                      \
               Bb + (size_t)r0 * K3 + kb + c0);                                       \
    cp_async16(sB + (s) * 128 * APAD * 2 + (r1 * APAD + c0) * 2,                      \
               Bb + (size_t)r1 * K3 + kb + c0);                                       \
    cp_commit();                                                                      \
} while (0)

    LOAD_STAGE(0, 0);

    // ldmatrix lane addressing (element offsets within a stage)
    const int a_row = wm + (lane & 15);          // + mi*16
    const int a_col = (lane >> 4) << 3;          // + ks*16
    const int b_row = ((lane >> 4) & 1) * 8 + (lane & 7);   // + wn + nj*16
    const int b_col = ((lane >> 3) & 1) << 3;               // + ks*16

    for (int kt = 0; kt < nk; kt++) {
        const int s = kt & 1;
        if (kt + 1 < nk) {
            LOAD_STAGE(kt + 1, s ^ 1);
            asm volatile("cp.async.wait_group 1;");
        } else {
            asm volatile("cp.async.wait_group 0;");
        }
        __syncthreads();

        const uint32_t aBase = sA + s * 128 * APAD * 2;
        const uint32_t bBase = sB + s * 128 * APAD * 2;
#pragma unroll
        for (int ks = 0; ks < 2; ks++) {
            uint32_t a[4][4], b[2][4];
#pragma unroll
            for (int mi = 0; mi < 4; mi++)
                ldmatrix_x4(a[mi][0], a[mi][1], a[mi][2], a[mi][3],
                            aBase + 2 * ((a_row + mi * 16) * APAD + ks * 16 + a_col));
#pragma unroll
            for (int nj = 0; nj < 2; nj++)
                ldmatrix_x4(b[nj][0], b[nj][1], b[nj][2], b[nj][3],
                            bBase + 2 * ((wn + nj * 16 + b_row) * APAD + ks * 16 + b_col));
#pragma unroll
            for (int mi = 0; mi < 4; mi++)
#pragma unroll
                for (int nt = 0; nt < 4; nt++)
                    mma16816(acc[mi][nt], a[mi], &b[nt >> 1][(nt & 1) * 2]);
        }
        __syncthreads();
    }

    // epilogue
    const int g = lane >> 2, tl = lane & 3;
#pragma unroll
    for (int mi = 0; mi < 4; mi++) {
#pragma unroll
        for (int nt = 0; nt < 4; nt++) {
            int row = bm + wm + mi * 16 + g;
            int col = bn + wn + nt * 8 + tl * 2;
            *(float2*)(C + (size_t)row * N + col) =
                make_float2(acc[mi][nt][0], acc[mi][nt][1]);
            *(float2*)(C + (size_t)(row + 8) * N + col) =
                make_float2(acc[mi][nt][2], acc[mi][nt][3]);
        }
    }
#undef LOAD_STAGE
}

// ================= conversion kernels =================
__global__ __launch_bounds__(256) void conv_cat_A(
    const float* __restrict__ X, __nv_bfloat16* __restrict__ Y, int K)
{
    const int row = blockIdx.x;
    const float* xr = X + (size_t)row * K;
    __nv_bfloat16* yr = Y + (size_t)row * 3 * K;
    for (int c = threadIdx.x; c < K; c += 256) {
        __nv_bfloat16 h, l;
        split_bf16(xr[c], h, l);
        yr[c] = h; yr[K + c] = l; yr[2 * K + c] = h;
    }
}
__global__ __launch_bounds__(256) void convT_cat_B(
    const float* __restrict__ W, __nv_bfloat16* __restrict__ Y, int K, int N)
{
    __shared__ float s[32][33];
    const int tx = threadIdx.x & 31, ty = threadIdx.x >> 5;
    const int n0 = blockIdx.x << 5, k0 = blockIdx.y << 5;
#pragma unroll
    for (int i = 0; i < 4; i++)
        s[ty + 8 * i][tx] = W[(size_t)(k0 + ty + 8 * i) * N + n0 + tx];
    __syncthreads();
#pragma unroll
    for (int i = 0; i < 4; i++) {
        int n = n0 + ty + 8 * i, k = k0 + tx;
        __nv_bfloat16 h, l;
        split_bf16(s[tx][ty + 8 * i], h, l);
        __nv_bfloat16* yr = Y + (size_t)n * 3 * K;
        yr[k] = h; yr[K + k] = h; yr[2 * K + k] = l;
    }
}

// ---------------- rope cos/sin table ----------------
__global__ void rope_table_kernel(const int* __restrict__ pos,
                                  float* __restrict__ cosT, float* __restrict__ sinT)
{
    int s = blockIdx.x, i = threadIdx.x;
    double e = (double)i / 64.0;
    float t = (float)pow(10000.0, e);
    float freq = (1.0f / t) * 40.0f;
    float ang = (float)pos[s] * freq;
    cosT[s * 64 + i] = (float)cos((double)ang);
    sinT[s * 64 + i] = (float)sin((double)ang);
}

// ---------------- layernorm + rope ----------------
__global__ __launch_bounds__(256) void ln_rope_kernel(
    const float* __restrict__ KV, const float* __restrict__ lnscale,
    float* __restrict__ Q, __nv_bfloat16* __restrict__ KVCc, float* __restrict__ KPE,
    const float* __restrict__ cosT, const float* __restrict__ sinT)
{
    const int row = blockIdx.x;
    const int tid = threadIdx.x;
    const int s = row & (S_ - 1);
    const float* kvr = KV + (size_t)row * 768;

    float v0 = kvr[tid], v1 = kvr[tid + 256];
    float sum = v0 + v1, sq = v0 * v0 + v1 * v1;
#pragma unroll
    for (int o = 16; o > 0; o >>= 1) {
        sum += __shfl_xor_sync(0xffffffffu, sum, o);
        sq  += __shfl_xor_sync(0xffffffffu, sq, o);
    }
    __shared__ float red[16];
    if ((tid & 31) == 0) { red[tid >> 5] = sum; red[(tid >> 5) + 8] = sq; }
    __syncthreads();
    float tot = 0.f, tot2 = 0.f;
#pragma unroll
    for (int i = 0; i < 8; i++) { tot += red[i]; tot2 += red[i + 8]; }
    float mean = tot * (1.f / 512.f);
    float var  = tot2 * (1.f / 512.f) - mean * mean;
    float inv  = rsqrtf(var + 1e-5f);
    float y0 = (v0 - mean) * inv * lnscale[tid];
    float y1 = (v1 - mean) * inv * lnscale[tid + 256];
    {
        __nv_bfloat16 h, l;
        __nv_bfloat16* yr = KVCc + (size_t)row * 1536;
        split_bf16(y0, h, l);
        yr[tid] = h; yr[512 + tid] = l; yr[1024 + tid] = h;
        split_bf16(y1, h, l);
        yr[tid + 256] = h; yr[512 + tid + 256] = l; yr[1024 + tid + 256] = h;
    }

    if (tid < 64) {
        float c = cosT[s * 64 + tid], sn = sinT[s * 64 + tid];
        float xr = kvr[512 + 2 * tid], xi = kvr[512 + 2 * tid + 1];
        KPE[(size_t)row * 128 + 2 * tid]     = xr * c - xi * sn;
        KPE[(size_t)row * 128 + 2 * tid + 1] = xr * sn + xi * c;
    }
#pragma unroll
    for (int t = tid; t < 1024; t += 256) {
        int hh = t >> 6, i = t & 63;
        float c = cosT[s * 64 + i], sn = sinT[s * 64 + i];
        float* qp = Q + (size_t)row * 4096 + hh * 256 + 128 + 2 * i;
        float xr = qp[0], xi = qp[1];
        qp[0] = xr * c - xi * sn;
        qp[1] = xr * sn + xi * c;
    }
}

// ---------------- flash attention (causal, online softmax, fp32) ----------------
#define QKS 68
#define FLASH_SMEM ((2 * 256 * QKS + 64 * 128 + 64 * 68) * 4)

__global__ __launch_bounds__(256) void flash_kernel(
    const float* __restrict__ Q, const float* __restrict__ KVB,
    const float* __restrict__ KPE, __nv_bfloat16* __restrict__ ATTNc)
{
    extern __shared__ float smf[];
    float* Qs = smf;
    float* Ks = Qs + 256 * QKS;
    float* Vs = Ks + 256 * QKS;
    float* Ps = Vs + 64 * 128;

    const int tid = threadIdx.x;
    const int tx = tid & 15, ty = tid >> 4;
    const int qi = blockIdx.x, hh = blockIdx.y, b = blockIdx.z;
    const int kvh = hh >> 1;
    const int qb = b * S_ + qi * 64;

#pragma unroll
    for (int l = 0; l < 16; l++) {
        int f = tid + (l << 8);
        int r = f & 63, c = f >> 6;
        float4 v = *(const float4*)(Q + (size_t)(qb + r) * 4096 + hh * 256 + c * 4);
        Qs[(c * 4 + 0) * QKS + r] = v.x;
        Qs[(c * 4 + 1) * QKS + r] = v.y;
        Qs[(c * 4 + 2) * QKS + r] = v.z;
        Qs[(c * 4 + 3) * QKS + r] = v.w;
    }

    float m[4], lsum[4], o[4][8];
#pragma unroll
    for (int i = 0; i < 4; i++) {
        m[i] = -INFINITY; lsum[i] = 0.f;
#pragma unroll
        for (int j = 0; j < 8; j++) o[i][j] = 0.f;
    }
    const float scale = 0.08838834764831845f;

    for (int kt = 0; kt <= qi; kt++) {
        const int kb = b * S_ + kt * 64;
        __syncthreads();
#pragma unroll
        for (int l = 0; l < 16; l++) {
            int f = tid + (l << 8);
            int r = f & 63, c = f >> 6;
            float4 v;
            if (c < 32)
                v = *(const float4*)(KVB + (size_t)(kb + r) * 2048 + kvh * 256 + c * 4);
            else
                v = *(const float4*)(KPE + (size_t)(kb + r) * 128 + (c - 32) * 4);
            Ks[(c * 4 + 0) * QKS + r] = v.x;
            Ks[(c * 4 + 1) * QKS + r] = v.y;
            Ks[(c * 4 + 2) * QKS + r] = v.z;
            Ks[(c * 4 + 3) * QKS + r] = v.w;
        }
#pragma unroll
        for (int l = 0; l < 8; l++) {
            int f = tid + (l << 8);
            int r = f >> 5, c = (f & 31) << 2;
            *(float4*)(Vs + r * 128 + c) =
                *(const float4*)(KVB + (size_t)(kb + r) * 2048 + kvh * 256 + 128 + c);
        }
        __syncthreads();

        float s[4][4] = {};
#pragma unroll 8
        for (int d = 0; d < 256; d++) {
            float4 q4 = *(const float4*)(Qs + d * QKS + ty * 4);
            float kvv[4];
#pragma unroll
            for (int j = 0; j < 4; j++) kvv[j] = Ks[d * QKS + tx + (j << 4)];
            s[0][0] = fmaf(q4.x, kvv[0], s[0][0]); s[0][1] = fmaf(q4.x, kvv[1], s[0][1]);
            s[0][2] = fmaf(q4.x, kvv[2], s[0][2]); s[0][3] = fmaf(q4.x, kvv[3], s[0][3]);
            s[1][0] = fmaf(q4.y, kvv[0], s[1][0]); s[1][1] = fmaf(q4.y, kvv[1], s[1][1]);
            s[1][2] = fmaf(q4.y, kvv[2], s[1][2]); s[1][3] = fmaf(q4.y, kvv[3], s[1][3]);
            s[2][0] = fmaf(q4.z, kvv[0], s[2][0]); s[2][1] = fmaf(q4.z, kvv[1], s[2][1]);
            s[2][2] = fmaf(q4.z, kvv[2], s[2][2]); s[2][3] = fmaf(q4.z, kvv[3], s[2][3]);
            s[3][0] = fmaf(q4.w, kvv[0], s[3][0]); s[3][1] = fmaf(q4.w, kvv[1], s[3][1]);
            s[3][2] = fmaf(q4.w, kvv[2], s[3][2]); s[3][3] = fmaf(q4.w, kvv[3], s[3][3]);
        }

        const bool diag = (kt == qi);
#pragma unroll
        for (int i = 0; i < 4; i++) {
            float mt;
#pragma unroll
            for (int j = 0; j < 4; j++) {
                s[i][j] *= scale;
                if (diag && (tx + (j << 4)) > (ty * 4 + i)) s[i][j] = -1e9f;
            }
            mt = fmaxf(fmaxf(s[i][0], s[i][1]), fmaxf(s[i][2], s[i][3]));
#pragma unroll
            for (int ofs = 8; ofs > 0; ofs >>= 1)
                mt = fmaxf(mt, __shfl_xor_sync(0xffffffffu, mt, ofs));
            float mnew = fmaxf(m[i], mt);
            float alpha = __expf(m[i] - mnew);
            float rs = 0.f;
#pragma unroll
            for (int j = 0; j < 4; j++) {
                float p = __expf(s[i][j] - mnew);
                rs += p;
                Ps[(ty * 4 + i) * 68 + tx + (j << 4)] = p;
            }
#pragma unroll
            for (int ofs = 8; ofs > 0; ofs >>= 1)
                rs += __shfl_xor_sync(0xffffffffu, rs, ofs);
            lsum[i] = lsum[i] * alpha + rs;
            m[i] = mnew;
#pragma unroll
            for (int j = 0; j < 8; j++) o[i][j] *= alpha;
        }
        __syncthreads();

#pragma unroll 4
        for (int k = 0; k < 64; k++) {
            float pv[4];
#pragma unroll
            for (int i = 0; i < 4; i++) pv[i] = Ps[(ty * 4 + i) * 68 + k];
#pragma unroll
            for (int j = 0; j < 8; j++) {
                float vv = Vs[k * 128 + tx + (j << 4)];
#pragma unroll
                for (int i = 0; i < 4; i++) o[i][j] = fmaf(pv[i], vv, o[i][j]);
            }
        }
    }

    // epilogue: write bf16 split-cat [4096, 6144] = [hi, lo, hi]
#pragma unroll
    for (int i = 0; i < 4; i++) {
        float inv = 1.f / lsum[i];
        __nv_bfloat16* base = ATTNc + (size_t)(qb + ty * 4 + i) * 6144 + hh * 128;
#pragma unroll
        for (int j = 0; j < 8; j++) {
            float val = o[i][j] * inv;
            __nv_bfloat16 hb, lb;
            split_bf16(val, hb, lb);
            int col = tx + (j << 4);
            base[col] = hb; base[2048 + col] = lb; base[4096 + col] = hb;
        }
    }
}

// ---------------- launcher ----------------
extern "C" void kernel_launch(void* const* d_in, const int* in_sizes, int n_in,
                              void* d_out, int out_size)
{
    const float* x        = (const float*)d_in[0];
    const float* wq       = (const float*)d_in[1];
    const float* wkv_a    = (const float*)d_in[2];
    const float* kv_scale = (const float*)d_in[3];
    const float* wkv_b    = (const float*)d_in[4];
    const float* wo       = (const float*)d_in[5];
    const int* pos        = (const int*)d_in[7];
    float* out            = (float*)d_out;

    float *Q, *KV, *KPE, *KVB, *cosT, *sinT;
    __nv_bfloat16 *Xc, *KVCc, *ATTNc, *WqT, *WkvaT, *WkvbT, *WoT;
    cudaGetSymbolAddress((void**)&Q,     g_Q);
    cudaGetSymbolAddress((void**)&KV,    g_KV);
    cudaGetSymbolAddress((void**)&KPE,   g_KPE);
    cudaGetSymbolAddress((void**)&KVB,   g_KVB);
    cudaGetSymbolAddress((void**)&cosT,  g_COS);
    cudaGetSymbolAddress((void**)&sinT,  g_SIN);
    cudaGetSymbolAddress((void**)&Xc,    g_Xc);
    cudaGetSymbolAddress((void**)&KVCc,  g_KVCc);
    cudaGetSymbolAddress((void**)&ATTNc, g_ATTNc);
    cudaGetSymbolAddress((void**)&WqT,   g_WqT);
    cudaGetSymbolAddress((void**)&WkvaT, g_WkvaT);
    cudaGetSymbolAddress((void**)&WkvbT, g_WkvbT);
    cudaGetSymbolAddress((void**)&WoT,   g_WoT);

    cudaFuncSetAttribute(flash_kernel,
                         cudaFuncAttributeMaxDynamicSharedMemorySize, FLASH_SMEM);

    dim3 blk(256);
    // conversions
    conv_cat_A<<<NROWS, blk>>>(x, Xc, 2048);
    convT_cat_B<<<dim3(4096 / 32, 2048 / 32), blk>>>(wq, WqT, 2048, 4096);
    convT_cat_B<<<dim3(640 / 32, 2048 / 32), blk>>>(wkv_a, WkvaT, 2048, 640);
    convT_cat_B<<<dim3(2048 / 32, 512 / 32), blk>>>(wkv_b, WkvbT, 512, 2048);
    convT_cat_B<<<dim3(2048 / 32, 2048 / 32), blk>>>(wo, WoT, 2048, 2048);
    rope_table_kernel<<<S_, 64>>>(pos, cosT, sinT);
    // q proj: [4096,4096] = Xc @ WqT^T
    mma_gemm<<<dim3(32, 32), blk>>>(Xc, WqT, Q, 4096, 6144);
    // kv_a proj: [4096,768(pad)] — cols >=640 garbage, never read
    mma_gemm<<<dim3(6, 32), blk>>>(Xc, WkvaT, KV, 768, 6144);
    ln_rope_kernel<<<NROWS, blk>>>(KV, kv_scale, Q, KVCc, KPE, cosT, sinT);
    // kv_b proj: [4096,2048]
    mma_gemm<<<dim3(16, 32), blk>>>(KVCc, WkvbT, KVB, 2048, 1536);
    flash_kernel<<<dim3(32, H_, B_), blk, FLASH_SMEM>>>(Q, KVB, KPE, ATTNc);
    // out proj: [4096,2048]
    mma_gemm<<<dim3(16, 32), blk>>>(ATTNc, WoT, out, 2048, 6144);
}